// round 9
// baseline (speedup 1.0000x reference)
#include <cuda_runtime.h>

// 2-layer LSTM: layer1 D=1 -> H=36, ReLU, layer2 36 -> 1. B=2048, T=2048, fp32.
// 512 blocks x 160 threads, 4 batches/block, target 4 blocks/SM (independent
// pipelines; plain __syncthreads, 7-cyc):
//   tids 0..143 (warps 0..4 lanes 0..15): layer1. thread=(j=tid>>2, kq=tid&3),
//     9 k-steps x 4 gates x 4 batches packed f32x2; quad reduce-scatter
//     (xor2,xor1) -> lane owns batch kq. 5 MUFU activations.
//   tids 144..159 (warp 4 lanes 16..31): layer2 (4 gates x 4 k-segs).
// h duplicated {h,h}, row stride 12 floats.

#define TT   2048
#define H    36
#define HS   12
#define BPB  4
#define NT   160
#define TCH  64

typedef unsigned long long u64;

__device__ __forceinline__ u64 pk2(float lo, float hi) {
    u64 r; asm("mov.b64 %0,{%1,%2};" : "=l"(r) : "f"(lo), "f"(hi)); return r;
}
__device__ __forceinline__ void upk2(u64 v, float& lo, float& hi) {
    asm("mov.b64 {%0,%1},%2;" : "=f"(lo), "=f"(hi) : "l"(v));
}
__device__ __forceinline__ u64 fma2(u64 a, u64 b, u64 c) {
    u64 d; asm("fma.rn.f32x2 %0,%1,%2,%3;" : "=l"(d) : "l"(a), "l"(b), "l"(c)); return d;
}
__device__ __forceinline__ u64 add2(u64 a, u64 b) {
    u64 d; asm("add.rn.f32x2 %0,%1,%2;" : "=l"(d) : "l"(a), "l"(b)); return d;
}
__device__ __forceinline__ u64 shfl64(unsigned m, u64 v, int lx) {
    return __shfl_xor_sync(m, v, lx);
}
__device__ __forceinline__ float tanhap(float x) {
    float y; asm("tanh.approx.f32 %0,%1;" : "=f"(y) : "f"(x)); return y;
}
__device__ __forceinline__ float sigap(float x) {
    return fmaf(0.5f, tanhap(0.5f * x), 0.5f);
}

__global__ void __launch_bounds__(NT, 4) lstm2_kernel(
    const float* __restrict__ x,
    const float* __restrict__ Wih1, const float* __restrict__ Whh1,
    const float* __restrict__ bih1, const float* __restrict__ bhh1,
    const float* __restrict__ Wih2, const float* __restrict__ Whh2,
    const float* __restrict__ bih2, const float* __restrict__ bhh2,
    float* __restrict__ out)
{
    // duplicated h: hsm[buf][unit][2b+{0,1}] = h(batch b), b in 0..3
    __shared__ __align__(16) float hsm[2][H][HS];
    __shared__ float xsm[BPB][TCH];
    __shared__ float osm[BPB][TCH];

    const int tid   = threadIdx.x;
    const int bbase = blockIdx.x * BPB;
    const bool isL1 = (tid < 144);
    const unsigned lmask = ((tid >> 5) == 4)
                         ? (isL1 ? 0x0000FFFFu : 0xFFFF0000u)
                         : 0xFFFFFFFFu;

    for (int i = tid; i < 2 * H * HS; i += NT) (&hsm[0][0][0])[i] = 0.0f;

    // ---- layer-1 identity + register weights ----
    int j = 0, kq = 0;
    u64 w1p[9][2];                   // packed {w_i,w_f},{w_g,w_o} per k
    u64 bias0 = 0, bias1 = 0;        // packed biases, only on kq==0 lanes
    float wx0=0, wx1=0, wx2=0, wx3=0;
    float c1 = 0.0f;
    if (isL1) {
        j = tid >> 2; kq = tid & 3;
        const int kb = kq * 9;
        #pragma unroll
        for (int kk = 0; kk < 9; ++kk) {
            const int k = kb + kk;
            w1p[kk][0] = pk2(Whh1[j * H + k],           Whh1[(H + j) * H + k]);
            w1p[kk][1] = pk2(Whh1[(2 * H + j) * H + k], Whh1[(3 * H + j) * H + k]);
        }
        wx0 = Wih1[j]; wx1 = Wih1[H + j]; wx2 = Wih1[2 * H + j]; wx3 = Wih1[3 * H + j];
        if (kq == 0) {
            bias0 = pk2(bih1[j] + bhh1[j],                 bih1[H + j] + bhh1[H + j]);
            bias1 = pk2(bih1[2 * H + j] + bhh1[2 * H + j], bih1[3 * H + j] + bhh1[3 * H + j]);
        }
    }

    // ---- layer-2 identity (warp 4 lanes 16..31) ----
    int g2 = 0, sg = 0, l2l = 0;
    float w2r[9]; float b2 = 0.0f, wh2g = 0.0f;
    float sA = 1.0f, sQ = 1.0f, sR = 0.0f;   // act(v) = sR + sQ*tanh(sA*v)
    float c2[4] = {0, 0, 0, 0}, h2[4] = {0, 0, 0, 0};
    if (!isL1) {
        l2l = tid - 144; g2 = l2l & 3; sg = l2l >> 2;
        #pragma unroll
        for (int s = 0; s < 9; ++s) w2r[s] = Wih2[g2 * H + sg * 9 + s];
        b2 = (sg == 0) ? (bih2[g2] + bhh2[g2]) : 0.0f;
        wh2g = Whh2[g2];
        if (g2 != 2) { sA = 0.5f; sQ = 0.5f; sR = 0.5f; }
    }
    __syncthreads();

    int cur = 0;
    for (int t = 0; t <= TT; ++t) {
        const int ti = t & (TCH - 1);
        if (ti == 0 && t < TT) {
            __syncthreads();
            for (int idx = tid; idx < BPB * TCH; idx += NT) {
                const int b = idx >> 6, i2 = idx & (TCH - 1);
                xsm[b][i2] = x[(bbase + b) * TT + t + i2];
            }
            __syncthreads();
        } else if (ti == 1 && t > TCH) {
            __syncthreads();
            const int tb = t - (TCH + 1);
            for (int idx = tid; idx < BPB * TCH; idx += NT) {
                const int b = idx >> 6, i2 = idx & (TCH - 1);
                out[(bbase + b) * TT + tb + i2] = osm[b][i2];
            }
            __syncthreads();
        }

        if (isL1 && t < TT) {
            // ---- matvec: 9 k-steps, 4 batches, packed gate pairs ----
            u64 a0[4], a1[4];
            a0[0] = bias0; a0[1] = bias0; a0[2] = bias0; a0[3] = bias0;
            a1[0] = bias1; a1[1] = bias1; a1[2] = bias1; a1[3] = bias1;
            const int kb = kq * 9;
            #pragma unroll
            for (int kk = 0; kk < 9; ++kk) {
                const ulonglong2 p01 = *(const ulonglong2*)&hsm[cur][kb + kk][0];
                const ulonglong2 p23 = *(const ulonglong2*)&hsm[cur][kb + kk][4];
                const u64 wA = w1p[kk][0], wB = w1p[kk][1];
                a0[0] = fma2(wA, p01.x, a0[0]); a1[0] = fma2(wB, p01.x, a1[0]);
                a0[1] = fma2(wA, p01.y, a0[1]); a1[1] = fma2(wB, p01.y, a1[1]);
                a0[2] = fma2(wA, p23.x, a0[2]); a1[2] = fma2(wB, p23.x, a1[2]);
                a0[3] = fma2(wA, p23.y, a0[3]); a1[3] = fma2(wB, p23.y, a1[3]);
            }
            // ---- quad reduce-scatter: round 1 over xor 2 ----
            const bool hi2 = (kq & 2) != 0;
            u64 s0 = hi2 ? a0[0] : a0[2];
            u64 s1 = hi2 ? a0[1] : a0[3];
            u64 s2 = hi2 ? a1[0] : a1[2];
            u64 s3 = hi2 ? a1[1] : a1[3];
            u64 k0 = hi2 ? a0[2] : a0[0];
            u64 k1 = hi2 ? a0[3] : a0[1];
            u64 k2 = hi2 ? a1[2] : a1[0];
            u64 k3 = hi2 ? a1[3] : a1[1];
            k0 = add2(k0, shfl64(lmask, s0, 2));
            k1 = add2(k1, shfl64(lmask, s1, 2));
            k2 = add2(k2, shfl64(lmask, s2, 2));
            k3 = add2(k3, shfl64(lmask, s3, 2));
            // ---- round 2 over xor 1: keep batch kq ----
            const bool hi1 = (kq & 1) != 0;
            u64 t0 = hi1 ? k0 : k1;
            u64 t1 = hi1 ? k2 : k3;
            u64 f0 = hi1 ? k1 : k0;   // {gate_i, gate_f} for batch kq
            u64 f1 = hi1 ? k3 : k2;   // {gate_g, gate_o}
            f0 = add2(f0, shfl64(lmask, t0, 1));
            f1 = add2(f1, shfl64(lmask, t1, 1));
            // ---- activations for batch bbase+kq ----
            float gi, gf, gg, go;
            upk2(f0, gi, gf);
            upk2(f1, gg, go);
            const float xb = xsm[kq][ti];
            gi = fmaf(wx0, xb, gi);
            gf = fmaf(wx1, xb, gf);
            gg = fmaf(wx2, xb, gg);
            go = fmaf(wx3, xb, go);
            const float cc = sigap(gf) * c1 + sigap(gi) * tanhap(gg);
            c1 = cc;
            const float hh = sigap(go) * tanhap(cc);
            *(float2*)&hsm[cur ^ 1][j][kq * 2] = make_float2(hh, hh);
        } else if (!isL1 && t >= 1) {
            // ---- layer 2 for time t-1 (lanes 16..31 of warp 4) ----
            float p0 = b2, p1 = b2, p2 = b2, p3 = b2;
            #pragma unroll
            for (int s = 0; s < 9; ++s) {
                const int row = sg * 9 + s;
                const float4 q01 = *(const float4*)&hsm[cur][row][0];
                const float4 q23 = *(const float4*)&hsm[cur][row][4];
                const float w = w2r[s];
                p0 = fmaf(w, fmaxf(q01.x, 0.f), p0);
                p1 = fmaf(w, fmaxf(q01.z, 0.f), p1);
                p2 = fmaf(w, fmaxf(q23.x, 0.f), p2);
                p3 = fmaf(w, fmaxf(q23.z, 0.f), p3);
            }
            // reduce over 4 k-segments (xor 4, xor 8 within upper half)
            #pragma unroll
            for (int off = 4; off <= 8; off <<= 1) {
                p0 += __shfl_xor_sync(0xFFFF0000u, p0, off);
                p1 += __shfl_xor_sync(0xFFFF0000u, p1, off);
                p2 += __shfl_xor_sync(0xFFFF0000u, p2, off);
                p3 += __shfl_xor_sync(0xFFFF0000u, p3, off);
            }
            // recurrent + activation
            float a0v = fmaf(sQ, tanhap(sA * (p0 + wh2g * h2[0])), sR);
            float a1v = fmaf(sQ, tanhap(sA * (p1 + wh2g * h2[1])), sR);
            float a2v = fmaf(sQ, tanhap(sA * (p2 + wh2g * h2[2])), sR);
            float a3v = fmaf(sQ, tanhap(sA * (p3 + wh2g * h2[3])), sR);
            // gather the 4 gates from lanes 16..19 (sg==0 copies hold full sums)
            float Gi0 = __shfl_sync(0xFFFF0000u, a0v, 16);
            float Gi1 = __shfl_sync(0xFFFF0000u, a1v, 16);
            float Gi2 = __shfl_sync(0xFFFF0000u, a2v, 16);
            float Gi3 = __shfl_sync(0xFFFF0000u, a3v, 16);
            float Gf0 = __shfl_sync(0xFFFF0000u, a0v, 17);
            float Gf1 = __shfl_sync(0xFFFF0000u, a1v, 17);
            float Gf2 = __shfl_sync(0xFFFF0000u, a2v, 17);
            float Gf3 = __shfl_sync(0xFFFF0000u, a3v, 17);
            float Gg0 = __shfl_sync(0xFFFF0000u, a0v, 18);
            float Gg1 = __shfl_sync(0xFFFF0000u, a1v, 18);
            float Gg2 = __shfl_sync(0xFFFF0000u, a2v, 18);
            float Gg3 = __shfl_sync(0xFFFF0000u, a3v, 18);
            float Go0 = __shfl_sync(0xFFFF0000u, a0v, 19);
            float Go1 = __shfl_sync(0xFFFF0000u, a1v, 19);
            float Go2 = __shfl_sync(0xFFFF0000u, a2v, 19);
            float Go3 = __shfl_sync(0xFFFF0000u, a3v, 19);
            c2[0] = Gf0 * c2[0] + Gi0 * Gg0;
            c2[1] = Gf1 * c2[1] + Gi1 * Gg1;
            c2[2] = Gf2 * c2[2] + Gi2 * Gg2;
            c2[3] = Gf3 * c2[3] + Gi3 * Gg3;
            h2[0] = Go0 * tanhap(c2[0]);
            h2[1] = Go1 * tanhap(c2[1]);
            h2[2] = Go2 * tanhap(c2[2]);
            h2[3] = Go3 * tanhap(c2[3]);
            if (l2l == 0) {
                const int slot = (t - 1) & (TCH - 1);
                osm[0][slot] = h2[0];
                osm[1][slot] = h2[1];
                osm[2][slot] = h2[2];
                osm[3][slot] = h2[3];
            }
        }

        __syncthreads();
        cur ^= 1;
    }

    // ---- flush final chunk [TT-TCH, TT) ----
    for (int idx = tid; idx < BPB * TCH; idx += NT) {
        const int b = idx >> 6, i2 = idx & (TCH - 1);
        out[(bbase + b) * TT + (TT - TCH) + i2] = osm[b][i2];
    }
}

extern "C" void kernel_launch(void* const* d_in, const int* in_sizes, int n_in,
                              void* d_out, int out_size) {
    (void)in_sizes; (void)n_in; (void)out_size;
    const float* x    = (const float*)d_in[0];
    const float* Wih1 = (const float*)d_in[1];
    const float* Whh1 = (const float*)d_in[2];
    const float* bih1 = (const float*)d_in[3];
    const float* bhh1 = (const float*)d_in[4];
    const float* Wih2 = (const float*)d_in[5];
    const float* Whh2 = (const float*)d_in[6];
    const float* bih2 = (const float*)d_in[7];
    const float* bhh2 = (const float*)d_in[8];
    float* out = (float*)d_out;

    lstm2_kernel<<<512, NT>>>(x, Wih1, Whh1, bih1, bhh1,
                              Wih2, Whh2, bih2, bhh2, out);
}